// round 5
// baseline (speedup 1.0000x reference)
#include <cuda_runtime.h>
#include <math.h>

#define GRID_R 128
#define NCELL (GRID_R*GRID_R*GRID_R)
#define NOISE_CAP 12000000   // 8 paths * 500k queries * 3 comps

// 128^3 cells x 8 channels (7 used + 1 pad) = 64 MiB static scratch
__device__ float g_grid[NCELL * 8];
// precomputed noise, layout [m][k*3+c]  (48 MiB)
__device__ float g_noise[NOISE_CAP];

__device__ __forceinline__ float gelu_f(float x) {
    float t = tanhf(0.7978845608028654f * (x + 0.044715f * x * x * x));
    return 0.5f * x * (1.0f + t);
}

// ---------------- packed f32x2 helpers (sm_103a FFMA2 path) ----------------
__device__ __forceinline__ unsigned long long pk2(float lo, float hi) {
    unsigned long long r;
    asm("mov.b64 %0, {%1, %2};" : "=l"(r) : "f"(lo), "f"(hi));
    return r;
}
__device__ __forceinline__ void upk2(unsigned long long v, float& lo, float& hi) {
    asm("mov.b64 {%0, %1}, %2;" : "=f"(lo), "=f"(hi) : "l"(v));
}
__device__ __forceinline__ unsigned long long ffma2(unsigned long long a,
                                                    unsigned long long b,
                                                    unsigned long long c) {
    unsigned long long d;
    asm("fma.rn.f32x2 %0, %1, %2, %3;" : "=l"(d) : "l"(a), "l"(b), "l"(c));
    return d;
}

// ---------------------------------------------------------------------------
// Kernel 1: zero the grid
// ---------------------------------------------------------------------------
__global__ void zero_grid_kernel() {
    unsigned i = blockIdx.x * blockDim.x + threadIdx.x;
    if (i < (unsigned)(NCELL * 2)) {
        reinterpret_cast<float4*>(g_grid)[i] = make_float4(0.f, 0.f, 0.f, 0.f);
    }
}

// ---------------------------------------------------------------------------
// threefry2x32 with key = (0, 42), matching jax.random.key(42)
// ---------------------------------------------------------------------------
__device__ __forceinline__ void tf_round(unsigned& v0, unsigned& v1, int r) {
    v0 += v1;
    v1 = __funnelshift_l(v1, v1, r);
    v1 ^= v0;
}

__device__ __forceinline__ uint2 threefry_0_42(unsigned x0, unsigned x1) {
    const unsigned k0 = 0u, k1 = 42u;
    const unsigned k2 = 0u ^ 42u ^ 0x1BD11BDAu;
    unsigned v0 = x0 + k0, v1 = x1 + k1;
    tf_round(v0, v1, 13); tf_round(v0, v1, 15); tf_round(v0, v1, 26); tf_round(v0, v1, 6);
    v0 += k1; v1 += k2 + 1u;
    tf_round(v0, v1, 17); tf_round(v0, v1, 29); tf_round(v0, v1, 16); tf_round(v0, v1, 24);
    v0 += k2; v1 += k0 + 2u;
    tf_round(v0, v1, 13); tf_round(v0, v1, 15); tf_round(v0, v1, 26); tf_round(v0, v1, 6);
    v0 += k0; v1 += k1 + 3u;
    tf_round(v0, v1, 17); tf_round(v0, v1, 29); tf_round(v0, v1, 16); tf_round(v0, v1, 24);
    v0 += k1; v1 += k2 + 4u;
    tf_round(v0, v1, 13); tf_round(v0, v1, 15); tf_round(v0, v1, 26); tf_round(v0, v1, 6);
    v0 += k2; v1 += k0 + 5u;
    return make_uint2(v0, v1);
}

// jax_threefry_partitionable=True: bits[j] = w0 ^ w1 of threefry(key, (0, j))
__device__ __forceinline__ unsigned tf_bits_partitionable(unsigned j) {
    uint2 r = threefry_0_42(0u, j);
    return r.x ^ r.y;
}

__device__ __forceinline__ float bits_to_normal(unsigned b) {
    float f = __uint_as_float((b >> 9) | 0x3f800000u) - 1.0f;
    float u = f * 2.0f - 0.99999994f;
    u = fmaxf(u, -0.99999994f);
    return 1.4142135623730951f * erfinvf(u);
}

// ---------------------------------------------------------------------------
// Kernel 2: fused p2g scatter (atomic-bound) + noise precompute (ALU-bound)
// ---------------------------------------------------------------------------
__device__ __forceinline__ void red_add_v4(float* addr, float a, float b, float c, float d) {
    asm volatile("red.global.add.v4.f32 [%0], {%1,%2,%3,%4};"
                 :: "l"(addr), "f"(a), "f"(b), "f"(c), "f"(d) : "memory");
}

__global__ __launch_bounds__(256) void p2g_noise_kernel(
    const float* __restrict__ src_ref,
    const float* __restrict__ src_curr,
    const float* __restrict__ Wf,
    const float* __restrict__ bf,
    int N, int M, int nP2G) {

    if ((int)blockIdx.x < nP2G) {
        // ---- particle-to-grid scatter ----
        int i = blockIdx.x * blockDim.x + threadIdx.x;
        if (i >= N) return;

        float xs0 = fminf(fmaxf(src_ref[3 * i + 0], 0.f), 1.f);
        float xs1 = fminf(fmaxf(src_ref[3 * i + 1], 0.f), 1.f);
        float xs2 = fminf(fmaxf(src_ref[3 * i + 2], 0.f), 1.f);
        float u0 = src_curr[3 * i + 0] - xs0;
        float u1 = src_curr[3 * i + 1] - xs1;
        float u2 = src_curr[3 * i + 2] - xs2;

        float f0 = gelu_f(bf[0] + u0 * Wf[0] + u1 * Wf[3] + u2 * Wf[6]);
        float f1 = gelu_f(bf[1] + u0 * Wf[1] + u1 * Wf[4] + u2 * Wf[7]);
        float f2 = gelu_f(bf[2] + u0 * Wf[2] + u1 * Wf[5] + u2 * Wf[8]);

        float cx = fminf(xs0 * 127.f, 126.999f);
        float cy = fminf(xs1 * 127.f, 126.999f);
        float cz = fminf(xs2 * 127.f, 126.999f);
        int bx = (int)cx, by = (int)cy, bz = (int)cz;
        float dx = cx - (float)bx, dy = cy - (float)by, dz = cz - (float)bz;

#pragma unroll
        for (int ox = 0; ox < 2; ox++) {
            float wx = ox ? dx : 1.f - dx;
#pragma unroll
            for (int oy = 0; oy < 2; oy++) {
                float wxy = wx * (oy ? dy : 1.f - dy);
#pragma unroll
                for (int oz = 0; oz < 2; oz++) {
                    float w = wxy * (oz ? dz : 1.f - dz);
                    int cell = ((((bx + ox) << 7) + (by + oy)) << 7) + (bz + oz);
                    float* p = g_grid + cell * 8;
                    red_add_v4(p,     f0 * w, f1 * w, f2 * w, w);
                    red_add_v4(p + 4, u0 * w, u1 * w, u2 * w, 0.f);
                }
            }
        }
    } else {
        // ---- noise precompute: g_noise[m*24 + k*3 + c] = 0.8*N(bits[(k*M+m)*3+c])
        int E = M * 24;
        if (E > NOISE_CAP) return;   // fallback handled in query kernel
        int tid = (blockIdx.x - nP2G) * blockDim.x + threadIdx.x;
        int stride = (gridDim.x - nP2G) * blockDim.x;
        for (int t = tid; t < E; t += stride) {
            int m  = t / 24;
            int kc = t - m * 24;
            int k  = kc / 3;
            int c  = kc - k * 3;
            unsigned j = ((unsigned)k * (unsigned)M + (unsigned)m) * 3u + (unsigned)c;
            g_noise[t] = 0.8f * bits_to_normal(tf_bits_partitionable(j));
        }
    }
}

// ---------------------------------------------------------------------------
// Kernel 3: 8-path trilinear gather + MLP decode (packed f32x2)
// ---------------------------------------------------------------------------
__global__ __launch_bounds__(128) void query_kernel(
    const float* __restrict__ xq_in,
    const float* __restrict__ W1, const float* __restrict__ b1,
    const float* __restrict__ W2, const float* __restrict__ b2,
    const float* __restrict__ W3, const float* __restrict__ b3,
    float* __restrict__ out, int M, int use_pre) {

    __shared__ float sW1t[24 * 64];   // [j][i], i contiguous (pairs 8B-aligned)
    __shared__ float sW2t[64 * 64];   // [j][i]
    __shared__ float sW3p[64 * 4];
    __shared__ float sb1[64], sb2[64], sb3[3];

    for (int t = threadIdx.x; t < 24 * 64; t += blockDim.x) {
        int j = t / 24, i = t % 24;
        sW1t[t] = W1[i * 64 + j];
    }
    for (int t = threadIdx.x; t < 64 * 64; t += blockDim.x) {
        int j = t >> 6, i = t & 63;
        sW2t[t] = W2[i * 64 + j];
    }
    for (int t = threadIdx.x; t < 192; t += blockDim.x) {
        int j = t / 3, c = t % 3;
        sW3p[j * 4 + c] = W3[t];
    }
    for (int t = threadIdx.x; t < 64; t += blockDim.x) {
        sb1[t] = b1[t];
        sb2[t] = b2[t];
    }
    if (threadIdx.x < 3) sb3[threadIdx.x] = b3[threadIdx.x];
    __syncthreads();

    int m = blockIdx.x * blockDim.x + threadIdx.x;
    if (m >= M) return;

    float xq0 = fminf(fmaxf(xq_in[3 * m + 0], 0.f), 1.f);
    float xq1 = fminf(fmaxf(xq_in[3 * m + 1], 0.f), 1.f);
    float xq2 = fminf(fmaxf(xq_in[3 * m + 2], 0.f), 1.f);
    float q0 = xq0 * 127.f, q1 = xq1 * 127.f, q2 = xq2 * 127.f;

    // packed accumulators: (ch0,ch1) (ch2,ch3) (ch4,ch5) (ch6,pad)
    unsigned long long acc01 = 0ull, acc23 = 0ull, acc45 = 0ull, acc67 = 0ull;

    const float* my_noise = g_noise + (size_t)m * 24;

#pragma unroll 2
    for (int kk = 0; kk < 8; kk++) {
        float nx, ny, nzc;
        if (use_pre) {
            nx  = my_noise[kk * 3 + 0];
            ny  = my_noise[kk * 3 + 1];
            nzc = my_noise[kk * 3 + 2];
        } else {
            unsigned jb = ((unsigned)kk * (unsigned)M + (unsigned)m) * 3u;
            nx  = 0.8f * bits_to_normal(tf_bits_partitionable(jb + 0u));
            ny  = 0.8f * bits_to_normal(tf_bits_partitionable(jb + 1u));
            nzc = 0.8f * bits_to_normal(tf_bits_partitionable(jb + 2u));
        }
        float px = q0 + nx, py = q1 + ny, pz = q2 + nzc;

        float fx = floorf(px), fy = floorf(py), fz = floorf(pz);
        float dx = px - fx, dy = py - fy, dz = pz - fz;
        int lx = (int)fx, ly = (int)fy, lz = (int)fz;
        int x0i = min(max(lx, 0), 127), x1i = min(max(lx + 1, 0), 127);
        int y0i = min(max(ly, 0), 127), y1i = min(max(ly + 1, 0), 127);
        int z0i = min(max(lz, 0), 127), z1i = min(max(lz + 1, 0), 127);
#pragma unroll
        for (int cx = 0; cx < 2; cx++) {
            int ix = cx ? x1i : x0i;
            float wx = cx ? dx : 1.f - dx;
#pragma unroll
            for (int cy = 0; cy < 2; cy++) {
                int iy = cy ? y1i : y0i;
                float wxy = wx * (cy ? dy : 1.f - dy);
#pragma unroll
                for (int cz = 0; cz < 2; cz++) {
                    int iz = cz ? z1i : z0i;
                    float w = wxy * (cz ? dz : 1.f - dz);
                    int cell = (((ix << 7) + iy) << 7) + iz;
                    const ulonglong2* g =
                        reinterpret_cast<const ulonglong2*>(g_grid + cell * 8);
                    ulonglong2 va = g[0];   // (f0,f1),(f2,d)
                    ulonglong2 vb = g[1];   // (u0,u1),(u2,0)
                    unsigned long long ws = pk2(w, w);
                    acc01 = ffma2(va.x, ws, acc01);
                    acc23 = ffma2(va.y, ws, acc23);
                    acc45 = ffma2(vb.x, ws, acc45);
                    acc67 = ffma2(vb.y, ws, acc67);  // hi lane = pad = 0
                }
            }
        }
    }

    float a0, a1, a2, a3, a4, a5, a6, apad;
    upk2(acc01, a0, a1);
    upk2(acc23, a2, a3);
    upk2(acc45, a4, a5);
    upk2(acc67, a6, apad);

    float r3 = a3 * 0.125f;
    float denom = fmaxf(r3, 1e-5f);
    float s = (r3 > 1e-5f) ? (0.125f / denom) : 0.f;

    float dec[24];
    dec[0] = a0 * s; dec[1] = a1 * s; dec[2] = a2 * s;
    float un0 = a4 * s, un1 = a5 * s, un2 = a6 * s;
    dec[3] = un0; dec[4] = un1; dec[5] = un2;

    // posenc: 3x __sincosf (args in [0,pi]) + double-angle for 2x and 4x
    const float PI = 3.14159265358979323846f;
    {
        float s1, c1;
        __sincosf(PI * xq0, &s1, &c1);
        float s2 = 2.f * s1 * c1, c2 = 1.f - 2.f * s1 * s1;
        float s4 = 2.f * s2 * c2, c4 = 1.f - 2.f * s2 * s2;
        dec[6] = s1; dec[9] = c1; dec[12] = s2; dec[15] = c2; dec[18] = s4; dec[21] = c4;
        __sincosf(PI * xq1, &s1, &c1);
        s2 = 2.f * s1 * c1; c2 = 1.f - 2.f * s1 * s1;
        s4 = 2.f * s2 * c2; c4 = 1.f - 2.f * s2 * s2;
        dec[7] = s1; dec[10] = c1; dec[13] = s2; dec[16] = c2; dec[19] = s4; dec[22] = c4;
        __sincosf(PI * xq2, &s1, &c1);
        s2 = 2.f * s1 * c1; c2 = 1.f - 2.f * s1 * s1;
        s4 = 2.f * s2 * c2; c4 = 1.f - 2.f * s2 * s2;
        dec[8] = s1; dec[11] = c1; dec[14] = s2; dec[17] = c2; dec[20] = s4; dec[23] = c4;
    }

    // pack dec into 12 f32x2 pairs
    unsigned long long decp[12];
#pragma unroll
    for (int i = 0; i < 12; i++) decp[i] = pk2(dec[2 * i], dec[2 * i + 1]);

    // Layer 1: 24 -> 64 via FFMA2 (12 packed MACs per neuron)
    unsigned long long h1p[32];
#pragma unroll
    for (int j2 = 0; j2 < 32; j2++) {
        float tj[2];
#pragma unroll
        for (int half = 0; half < 2; half++) {
            int j = j2 * 2 + half;
            const ulonglong2* w = reinterpret_cast<const ulonglong2*>(sW1t + j * 24);
            unsigned long long acc = pk2(sb1[j], 0.f);
#pragma unroll
            for (int i = 0; i < 6; i++) {
                ulonglong2 wv = w[i];
                acc = ffma2(decp[2 * i + 0], wv.x, acc);
                acc = ffma2(decp[2 * i + 1], wv.y, acc);
            }
            float lo, hi;
            upk2(acc, lo, hi);
            tj[half] = gelu_f(lo + hi);
        }
        h1p[j2] = pk2(tj[0], tj[1]);
    }

    // Layer 2 (64->64, FFMA2) fused with layer 3 (64->3)
    float r0 = sb3[0], r1 = sb3[1], r2 = sb3[2];
#pragma unroll 4
    for (int j = 0; j < 64; j++) {
        const ulonglong2* w = reinterpret_cast<const ulonglong2*>(sW2t + j * 64);
        unsigned long long acc = pk2(sb2[j], 0.f);
#pragma unroll
        for (int i = 0; i < 16; i++) {
            ulonglong2 wv = w[i];
            acc = ffma2(h1p[2 * i + 0], wv.x, acc);
            acc = ffma2(h1p[2 * i + 1], wv.y, acc);
        }
        float lo, hi;
        upk2(acc, lo, hi);
        float g = gelu_f(lo + hi);
        r0 += g * sW3p[j * 4 + 0];
        r1 += g * sW3p[j * 4 + 1];
        r2 += g * sW3p[j * 4 + 2];
    }

    out[3 * m + 0] = fminf(fmaxf(un0 + r0, 0.001f), 0.999f);
    out[3 * m + 1] = fminf(fmaxf(un1 + r1, 0.001f), 0.999f);
    out[3 * m + 2] = fminf(fmaxf(un2 + r2, 0.001f), 0.999f);
}

// ---------------------------------------------------------------------------
extern "C" void kernel_launch(void* const* d_in, const int* in_sizes, int n_in,
                              void* d_out, int out_size) {
    const float* xq  = (const float*)d_in[0];
    const float* xsr = (const float*)d_in[1];
    const float* xsc = (const float*)d_in[2];
    const float* Wf  = (const float*)d_in[3];
    const float* bf  = (const float*)d_in[4];
    const float* W1  = (const float*)d_in[5];
    const float* b1  = (const float*)d_in[6];
    const float* W2  = (const float*)d_in[7];
    const float* b2  = (const float*)d_in[8];
    const float* W3  = (const float*)d_in[9];
    const float* b3  = (const float*)d_in[10];
    int M = in_sizes[0] / 3;
    int N = in_sizes[1] / 3;

    int use_pre = (M * 24 <= NOISE_CAP) ? 1 : 0;
    int nP2G = (N + 255) / 256;
    int nNoise = use_pre ? 2048 : 0;

    zero_grid_kernel<<<(NCELL * 2 + 255) / 256, 256>>>();
    p2g_noise_kernel<<<nP2G + nNoise, 256>>>(xsr, xsc, Wf, bf, N, M, nP2G);
    query_kernel<<<(M + 127) / 128, 128>>>(xq, W1, b1, W2, b2, W3, b3,
                                           (float*)d_out, M, use_pre);
}

// round 7
// speedup vs baseline: 1.2176x; 1.2176x over previous
#include <cuda_runtime.h>
#include <math.h>

#define GRID_R 128
#define NCELL (GRID_R*GRID_R*GRID_R)

// 128^3 cells x 8 channels (7 used + 1 pad) = 64 MiB static scratch
__device__ float g_grid[NCELL * 8];

__device__ __forceinline__ float gelu_f(float x) {
    float t = tanhf(0.7978845608028654f * (x + 0.044715f * x * x * x));
    return 0.5f * x * (1.0f + t);
}

// ---------------- packed f32x2 helpers (sm_103a FFMA2 path) ----------------
__device__ __forceinline__ unsigned long long pk2(float lo, float hi) {
    unsigned long long r;
    asm("mov.b64 %0, {%1, %2};" : "=l"(r) : "f"(lo), "f"(hi));
    return r;
}
__device__ __forceinline__ void upk2(unsigned long long v, float& lo, float& hi) {
    asm("mov.b64 {%0, %1}, %2;" : "=f"(lo), "=f"(hi) : "l"(v));
}
__device__ __forceinline__ unsigned long long ffma2(unsigned long long a,
                                                    unsigned long long b,
                                                    unsigned long long c) {
    unsigned long long d;
    asm("fma.rn.f32x2 %0, %1, %2, %3;" : "=l"(d) : "l"(a), "l"(b), "l"(c));
    return d;
}

// ---------------------------------------------------------------------------
// Kernel 1: zero the grid (grid-stride, 8 float4 per thread)
// ---------------------------------------------------------------------------
__global__ void zero_grid_kernel() {
    float4* g = reinterpret_cast<float4*>(g_grid);
    unsigned stride = gridDim.x * blockDim.x;
    for (unsigned i = blockIdx.x * blockDim.x + threadIdx.x;
         i < (unsigned)(NCELL * 2); i += stride) {
        g[i] = make_float4(0.f, 0.f, 0.f, 0.f);
    }
}

// ---------------------------------------------------------------------------
// Kernel 2: particle-to-grid trilinear scatter (vector reductions)
// ---------------------------------------------------------------------------
__device__ __forceinline__ void red_add_v4(float* addr, float a, float b, float c, float d) {
    asm volatile("red.global.add.v4.f32 [%0], {%1,%2,%3,%4};"
                 :: "l"(addr), "f"(a), "f"(b), "f"(c), "f"(d) : "memory");
}

__global__ __launch_bounds__(256) void p2g_kernel(
    const float* __restrict__ src_ref,
    const float* __restrict__ src_curr,
    const float* __restrict__ Wf,
    const float* __restrict__ bf,
    int N) {
    int i = blockIdx.x * blockDim.x + threadIdx.x;
    if (i >= N) return;

    float xs0 = fminf(fmaxf(src_ref[3 * i + 0], 0.f), 1.f);
    float xs1 = fminf(fmaxf(src_ref[3 * i + 1], 0.f), 1.f);
    float xs2 = fminf(fmaxf(src_ref[3 * i + 2], 0.f), 1.f);
    float u0 = src_curr[3 * i + 0] - xs0;
    float u1 = src_curr[3 * i + 1] - xs1;
    float u2 = src_curr[3 * i + 2] - xs2;

    float f0 = gelu_f(bf[0] + u0 * Wf[0] + u1 * Wf[3] + u2 * Wf[6]);
    float f1 = gelu_f(bf[1] + u0 * Wf[1] + u1 * Wf[4] + u2 * Wf[7]);
    float f2 = gelu_f(bf[2] + u0 * Wf[2] + u1 * Wf[5] + u2 * Wf[8]);

    float cx = fminf(xs0 * 127.f, 126.999f);
    float cy = fminf(xs1 * 127.f, 126.999f);
    float cz = fminf(xs2 * 127.f, 126.999f);
    int bx = (int)cx, by = (int)cy, bz = (int)cz;
    float dx = cx - (float)bx, dy = cy - (float)by, dz = cz - (float)bz;

#pragma unroll
    for (int ox = 0; ox < 2; ox++) {
        float wx = ox ? dx : 1.f - dx;
#pragma unroll
        for (int oy = 0; oy < 2; oy++) {
            float wxy = wx * (oy ? dy : 1.f - dy);
#pragma unroll
            for (int oz = 0; oz < 2; oz++) {
                float w = wxy * (oz ? dz : 1.f - dz);
                int cell = ((((bx + ox) << 7) + (by + oy)) << 7) + (bz + oz);
                float* p = g_grid + cell * 8;
                red_add_v4(p,     f0 * w, f1 * w, f2 * w, w);
                red_add_v4(p + 4, u0 * w, u1 * w, u2 * w, 0.f);
            }
        }
    }
}

// ---------------------------------------------------------------------------
// threefry2x32 with key = (0, 42), matching jax.random.key(42)
// ---------------------------------------------------------------------------
__device__ __forceinline__ void tf_round(unsigned& v0, unsigned& v1, int r) {
    v0 += v1;
    v1 = __funnelshift_l(v1, v1, r);
    v1 ^= v0;
}

__device__ __forceinline__ uint2 threefry_0_42(unsigned x0, unsigned x1) {
    const unsigned k0 = 0u, k1 = 42u;
    const unsigned k2 = 0u ^ 42u ^ 0x1BD11BDAu;
    unsigned v0 = x0 + k0, v1 = x1 + k1;
    tf_round(v0, v1, 13); tf_round(v0, v1, 15); tf_round(v0, v1, 26); tf_round(v0, v1, 6);
    v0 += k1; v1 += k2 + 1u;
    tf_round(v0, v1, 17); tf_round(v0, v1, 29); tf_round(v0, v1, 16); tf_round(v0, v1, 24);
    v0 += k2; v1 += k0 + 2u;
    tf_round(v0, v1, 13); tf_round(v0, v1, 15); tf_round(v0, v1, 26); tf_round(v0, v1, 6);
    v0 += k0; v1 += k1 + 3u;
    tf_round(v0, v1, 17); tf_round(v0, v1, 29); tf_round(v0, v1, 16); tf_round(v0, v1, 24);
    v0 += k1; v1 += k2 + 4u;
    tf_round(v0, v1, 13); tf_round(v0, v1, 15); tf_round(v0, v1, 26); tf_round(v0, v1, 6);
    v0 += k2; v1 += k0 + 5u;
    return make_uint2(v0, v1);
}

// jax_threefry_partitionable=True: bits[j] = w0 ^ w1 of threefry(key, (0, j))
__device__ __forceinline__ unsigned tf_bits_partitionable(unsigned j) {
    uint2 r = threefry_0_42(0u, j);
    return r.x ^ r.y;
}

__device__ __forceinline__ float bits_to_normal(unsigned b) {
    float f = __uint_as_float((b >> 9) | 0x3f800000u) - 1.0f;
    float u = f * 2.0f - 0.99999994f;
    u = fmaxf(u, -0.99999994f);
    return 1.4142135623730951f * erfinvf(u);
}

// ---------------------------------------------------------------------------
// Kernel 3: inline noise + 8-path trilinear gather + MLP decode (FFMA2)
// ---------------------------------------------------------------------------
__global__ __launch_bounds__(256) void query_kernel(
    const float* __restrict__ xq_in,
    const float* __restrict__ W1, const float* __restrict__ b1,
    const float* __restrict__ W2, const float* __restrict__ b2,
    const float* __restrict__ W3, const float* __restrict__ b3,
    float* __restrict__ out, int M) {

    __shared__ float sW1t[24 * 64];   // [j][i], i contiguous (pairs 8B-aligned)
    __shared__ float sW2t[64 * 64];   // [j][i]
    __shared__ float sW3p[64 * 4];
    __shared__ float sb1[64], sb2[64], sb3[3];

    for (int t = threadIdx.x; t < 24 * 64; t += blockDim.x) {
        int j = t / 24, i = t % 24;
        sW1t[t] = W1[i * 64 + j];
    }
    for (int t = threadIdx.x; t < 64 * 64; t += blockDim.x) {
        int j = t >> 6, i = t & 63;
        sW2t[t] = W2[i * 64 + j];
    }
    for (int t = threadIdx.x; t < 192; t += blockDim.x) {
        int j = t / 3, c = t % 3;
        sW3p[j * 4 + c] = W3[t];
    }
    for (int t = threadIdx.x; t < 64; t += blockDim.x) {
        sb1[t] = b1[t];
        sb2[t] = b2[t];
    }
    if (threadIdx.x < 3) sb3[threadIdx.x] = b3[threadIdx.x];
    __syncthreads();

    int m = blockIdx.x * blockDim.x + threadIdx.x;
    if (m >= M) return;

    float xq0 = fminf(fmaxf(xq_in[3 * m + 0], 0.f), 1.f);
    float xq1 = fminf(fmaxf(xq_in[3 * m + 1], 0.f), 1.f);
    float xq2 = fminf(fmaxf(xq_in[3 * m + 2], 0.f), 1.f);
    float q0 = xq0 * 127.f, q1 = xq1 * 127.f, q2 = xq2 * 127.f;

    // packed accumulators: (ch0,ch1) (ch2,ch3) (ch4,ch5) (ch6,pad)
    unsigned long long acc01 = 0ull, acc23 = 0ull, acc45 = 0ull, acc67 = 0ull;

#pragma unroll 1
    for (int kk = 0; kk < 8; kk++) {
        unsigned jb = ((unsigned)kk * (unsigned)M + (unsigned)m) * 3u;
        float px = q0 + 0.8f * bits_to_normal(tf_bits_partitionable(jb + 0u));
        float py = q1 + 0.8f * bits_to_normal(tf_bits_partitionable(jb + 1u));
        float pz = q2 + 0.8f * bits_to_normal(tf_bits_partitionable(jb + 2u));

        float fx = floorf(px), fy = floorf(py), fz = floorf(pz);
        float dx = px - fx, dy = py - fy, dz = pz - fz;
        int lx = (int)fx, ly = (int)fy, lz = (int)fz;
        int x0i = min(max(lx, 0), 127), x1i = min(max(lx + 1, 0), 127);
        int y0i = min(max(ly, 0), 127), y1i = min(max(ly + 1, 0), 127);
        int z0i = min(max(lz, 0), 127), z1i = min(max(lz + 1, 0), 127);
#pragma unroll
        for (int cx = 0; cx < 2; cx++) {
            int ix = cx ? x1i : x0i;
            float wx = cx ? dx : 1.f - dx;
#pragma unroll
            for (int cy = 0; cy < 2; cy++) {
                int iy = cy ? y1i : y0i;
                float wxy = wx * (cy ? dy : 1.f - dy);
#pragma unroll
                for (int cz = 0; cz < 2; cz++) {
                    int iz = cz ? z1i : z0i;
                    float w = wxy * (cz ? dz : 1.f - dz);
                    int cell = (((ix << 7) + iy) << 7) + iz;
                    const ulonglong2* g =
                        reinterpret_cast<const ulonglong2*>(g_grid + cell * 8);
                    ulonglong2 va = g[0];   // (f0,f1),(f2,d)
                    ulonglong2 vb = g[1];   // (u0,u1),(u2,0)
                    unsigned long long ws = pk2(w, w);
                    acc01 = ffma2(va.x, ws, acc01);
                    acc23 = ffma2(va.y, ws, acc23);
                    acc45 = ffma2(vb.x, ws, acc45);
                    acc67 = ffma2(vb.y, ws, acc67);  // hi lane = pad = 0
                }
            }
        }
    }

    float a0, a1, a2, a3, a4, a5, a6, apad;
    upk2(acc01, a0, a1);
    upk2(acc23, a2, a3);
    upk2(acc45, a4, a5);
    upk2(acc67, a6, apad);

    float r3 = a3 * 0.125f;
    float denom = fmaxf(r3, 1e-5f);
    float s = (r3 > 1e-5f) ? (0.125f / denom) : 0.f;

    float dec[24];
    dec[0] = a0 * s; dec[1] = a1 * s; dec[2] = a2 * s;
    float un0 = a4 * s, un1 = a5 * s, un2 = a6 * s;
    dec[3] = un0; dec[4] = un1; dec[5] = un2;

    // posenc: 3x __sincosf (args in [0,pi]) + double-angle for 2x and 4x
    const float PI = 3.14159265358979323846f;
    {
        float s1, c1;
        __sincosf(PI * xq0, &s1, &c1);
        float s2 = 2.f * s1 * c1, c2 = 1.f - 2.f * s1 * s1;
        float s4 = 2.f * s2 * c2, c4 = 1.f - 2.f * s2 * s2;
        dec[6] = s1; dec[9] = c1; dec[12] = s2; dec[15] = c2; dec[18] = s4; dec[21] = c4;
        __sincosf(PI * xq1, &s1, &c1);
        s2 = 2.f * s1 * c1; c2 = 1.f - 2.f * s1 * s1;
        s4 = 2.f * s2 * c2; c4 = 1.f - 2.f * s2 * s2;
        dec[7] = s1; dec[10] = c1; dec[13] = s2; dec[16] = c2; dec[19] = s4; dec[22] = c4;
        __sincosf(PI * xq2, &s1, &c1);
        s2 = 2.f * s1 * c1; c2 = 1.f - 2.f * s1 * s1;
        s4 = 2.f * s2 * c2; c4 = 1.f - 2.f * s2 * s2;
        dec[8] = s1; dec[11] = c1; dec[14] = s2; dec[17] = c2; dec[20] = s4; dec[23] = c4;
    }

    // pack dec into 12 f32x2 pairs
    unsigned long long decp[12];
#pragma unroll
    for (int i = 0; i < 12; i++) decp[i] = pk2(dec[2 * i], dec[2 * i + 1]);

    // Layer 1: 24 -> 64 via FFMA2 (12 packed MACs per neuron)
    unsigned long long h1p[32];
#pragma unroll
    for (int j2 = 0; j2 < 32; j2++) {
        float tj[2];
#pragma unroll
        for (int half = 0; half < 2; half++) {
            int j = j2 * 2 + half;
            const ulonglong2* w = reinterpret_cast<const ulonglong2*>(sW1t + j * 24);
            unsigned long long acc = pk2(sb1[j], 0.f);
#pragma unroll
            for (int i = 0; i < 6; i++) {
                ulonglong2 wv = w[i];
                acc = ffma2(decp[2 * i + 0], wv.x, acc);
                acc = ffma2(decp[2 * i + 1], wv.y, acc);
            }
            float lo, hi;
            upk2(acc, lo, hi);
            tj[half] = gelu_f(lo + hi);
        }
        h1p[j2] = pk2(tj[0], tj[1]);
    }

    // Layer 2 (64->64, FFMA2) fused with layer 3 (64->3)
    float r0 = sb3[0], r1 = sb3[1], r2 = sb3[2];
#pragma unroll 4
    for (int j = 0; j < 64; j++) {
        const ulonglong2* w = reinterpret_cast<const ulonglong2*>(sW2t + j * 64);
        unsigned long long acc = pk2(sb2[j], 0.f);
#pragma unroll
        for (int i = 0; i < 16; i++) {
            ulonglong2 wv = w[i];
            acc = ffma2(h1p[2 * i + 0], wv.x, acc);
            acc = ffma2(h1p[2 * i + 1], wv.y, acc);
        }
        float lo, hi;
        upk2(acc, lo, hi);
        float g = gelu_f(lo + hi);
        r0 += g * sW3p[j * 4 + 0];
        r1 += g * sW3p[j * 4 + 1];
        r2 += g * sW3p[j * 4 + 2];
    }

    out[3 * m + 0] = fminf(fmaxf(un0 + r0, 0.001f), 0.999f);
    out[3 * m + 1] = fminf(fmaxf(un1 + r1, 0.001f), 0.999f);
    out[3 * m + 2] = fminf(fmaxf(un2 + r2, 0.001f), 0.999f);
}

// ---------------------------------------------------------------------------
extern "C" void kernel_launch(void* const* d_in, const int* in_sizes, int n_in,
                              void* d_out, int out_size) {
    const float* xq  = (const float*)d_in[0];
    const float* xsr = (const float*)d_in[1];
    const float* xsc = (const float*)d_in[2];
    const float* Wf  = (const float*)d_in[3];
    const float* bf  = (const float*)d_in[4];
    const float* W1  = (const float*)d_in[5];
    const float* b1  = (const float*)d_in[6];
    const float* W2  = (const float*)d_in[7];
    const float* b2  = (const float*)d_in[8];
    const float* W3  = (const float*)d_in[9];
    const float* b3  = (const float*)d_in[10];
    int M = in_sizes[0] / 3;
    int N = in_sizes[1] / 3;

    zero_grid_kernel<<<2048, 256>>>();
    p2g_kernel<<<(N + 255) / 256, 256>>>(xsr, xsc, Wf, bf, N);
    query_kernel<<<(M + 255) / 256, 256>>>(xq, W1, b1, W2, b2, W3, b3,
                                           (float*)d_out, M);
}